// round 13
// baseline (speedup 1.0000x reference)
#include <cuda_runtime.h>
#include <cuda_fp16.h>
#include <math.h>
#include <stdint.h>

// ----------------------------------------------------------------------------
// Problem constants
// ----------------------------------------------------------------------------
#define B      2
#define N_SEQ  2048
#define DIM    2048
#define HEADS  16
#define DHEAD  128
#define INNER  (HEADS * DHEAD)       // 2048
#define ROWS   (B * N_SEQ)           // 4096
#define NQKV   (3 * INNER)           // 6144 fused projection width

// ----------------------------------------------------------------------------
// Scratch (device globals; no allocations allowed)
// ----------------------------------------------------------------------------
__device__ __half g_xn  [ROWS * DIM];
__device__ __half g_qkv [ROWS * NQKV];
__device__ __half g_o   [ROWS * INNER];
__device__ __half g_wqkv[DIM * NQKV];
__device__ __half g_wo  [INNER * DIM];
__device__ float  g_cos [N_SEQ * DHEAD];
__device__ float  g_sin [N_SEQ * DHEAD];

// ----------------------------------------------------------------------------
// helpers
// ----------------------------------------------------------------------------
__device__ __forceinline__ uint32_t f2h2(float lo, float hi) {
    uint32_t r;
    asm("cvt.rn.f16x2.f32 %0, %1, %2;" : "=r"(r) : "f"(hi), "f"(lo));
    return r;
}

__device__ __forceinline__ uint32_t hmul2(uint32_t a, uint32_t b) {
    uint32_t r;
    asm("mul.rn.f16x2 %0, %1, %2;" : "=r"(r) : "r"(a), "r"(b));
    return r;
}

__device__ __forceinline__ float fex2(float x) {
    float y;
    asm("ex2.approx.ftz.f32 %0, %1;" : "=f"(y) : "f"(x));
    return y;
}

__device__ __forceinline__ void mma_f16(float* c, const uint32_t* a, const uint32_t* b) {
    asm volatile(
        "mma.sync.aligned.m16n8k16.row.col.f32.f16.f16.f32 "
        "{%0,%1,%2,%3},{%4,%5,%6,%7},{%8,%9},{%0,%1,%2,%3};"
        : "+f"(c[0]), "+f"(c[1]), "+f"(c[2]), "+f"(c[3])
        : "r"(a[0]), "r"(a[1]), "r"(a[2]), "r"(a[3]), "r"(b[0]), "r"(b[1]));
}

__device__ __forceinline__ void ldm_x4(uint32_t* d, uint32_t addr) {
    asm volatile("ldmatrix.sync.aligned.m8n8.x4.shared.b16 {%0,%1,%2,%3}, [%4];"
                 : "=r"(d[0]), "=r"(d[1]), "=r"(d[2]), "=r"(d[3]) : "r"(addr));
}
__device__ __forceinline__ void ldm_x4_t(uint32_t* d, uint32_t addr) {
    asm volatile("ldmatrix.sync.aligned.m8n8.x4.trans.shared.b16 {%0,%1,%2,%3}, [%4];"
                 : "=r"(d[0]), "=r"(d[1]), "=r"(d[2]), "=r"(d[3]) : "r"(addr));
}

__device__ __forceinline__ uint32_t smem_u32(const void* p) {
    uint32_t a;
    asm("{ .reg .u64 t; cvta.to.shared.u64 t, %1; cvt.u32.u64 %0, t; }"
        : "=r"(a) : "l"(p));
    return a;
}

__device__ __forceinline__ void cpa16(uint32_t saddr, const void* g) {
    asm volatile("cp.async.cg.shared.global [%0], [%1], 16;" :: "r"(saddr), "l"(g));
}
#define CPA_COMMIT() asm volatile("cp.async.commit_group;" ::: "memory")
#define CPA_WAIT0()  asm volatile("cp.async.wait_group 0;"  ::: "memory")

// ----------------------------------------------------------------------------
// Weight fp32 -> fp16 conversion (with column remap into fused buffers)
// ----------------------------------------------------------------------------
__global__ __launch_bounds__(256) void cvtw_kernel(
    const float* __restrict__ src, __half* __restrict__ dst,
    int src_ncols, int dst_ncols, int col_off, int n)
{
    const int idx = (blockIdx.x * 256 + threadIdx.x) * 4;
    if (idx >= n) return;
    const int r = idx / src_ncols;
    const int c = idx - r * src_ncols;
    float4 v = *(const float4*)(src + idx);
    *(uint2*)(dst + (size_t)r * dst_ncols + col_off + c) =
        make_uint2(f2h2(v.x, v.y), f2h2(v.z, v.w));
}

// ----------------------------------------------------------------------------
// cos/sin table precompute (same cosf/sinf bits as before)
// ----------------------------------------------------------------------------
__global__ __launch_bounds__(256) void sincos_kernel(
    const float* __restrict__ re, float* __restrict__ ct, float* __restrict__ st)
{
    const int i = blockIdx.x * 256 + threadIdx.x;
    if (i < N_SEQ * DHEAD) {
        const float p = re[i];
        ct[i] = cosf(p);
        st[i] = sinf(p);
    }
}

// ----------------------------------------------------------------------------
// RMSNorm -> fp16 output (float4 path)
// ----------------------------------------------------------------------------
__global__ __launch_bounds__(256) void rmsnorm_kernel(
    const float* __restrict__ x, const float* __restrict__ g,
    __half* __restrict__ xn)
{
    const int row = blockIdx.x;
    const float* xr = x  + (size_t)row * DIM;
    __half*      xo = xn + (size_t)row * DIM;

    float ss = 0.f;
    #pragma unroll
    for (int i = threadIdx.x * 4; i < DIM; i += 1024) {
        float4 v = *(const float4*)(xr + i);
        ss += v.x * v.x + v.y * v.y + v.z * v.z + v.w * v.w;
    }
    __shared__ float red[8];
    #pragma unroll
    for (int o = 16; o > 0; o >>= 1) ss += __shfl_xor_sync(0xffffffffu, ss, o);
    if ((threadIdx.x & 31) == 0) red[threadIdx.x >> 5] = ss;
    __syncthreads();
    if (threadIdx.x < 8) {
        float v = red[threadIdx.x];
        #pragma unroll
        for (int o = 4; o > 0; o >>= 1) v += __shfl_xor_sync(0x000000ffu, v, o);
        if (threadIdx.x == 0) red[0] = v;
    }
    __syncthreads();
    const float rms = sqrtf(red[0] * (1.f / (float)DIM));
    const float inv = 1.f / fmaxf(rms, 1e-8f);
    #pragma unroll
    for (int i = threadIdx.x * 4; i < DIM; i += 1024) {
        float4 v = *(const float4*)(xr + i);
        float4 gg = *(const float4*)(g + i);
        *(uint2*)(xo + i) = make_uint2(
            f2h2(v.x * inv * gg.x, v.y * inv * gg.y),
            f2h2(v.z * inv * gg.z, v.w * inv * gg.w));
    }
}

// ----------------------------------------------------------------------------
// FP16 tensor-core GEMM (m16n8k16), cp.async double-buffered, ldmatrix.
// ----------------------------------------------------------------------------
#define G_BK 32
#define G_SA 40
#define G_SB 136
#define G_ABUF (128 * G_SA * 2)     // bytes per A stage
#define G_BBUF (G_BK * G_SB * 2)    // bytes per B stage

template <typename OutT>
__global__ __launch_bounds__(256, 2) void h16_gemm_kernel(
    int M, int N, int K,
    const __half* __restrict__ A, const __half* __restrict__ Bm,
    OutT* __restrict__ C)
{
    __shared__ __half As[2][128][G_SA];
    __shared__ __half Bs[2][G_BK][G_SB];

    const int tid  = threadIdx.x;
    const int lane = tid & 31;
    const int warp = tid >> 5;
    const int mbase = (warp >> 1) * 32;
    const int nbase = (warp & 1) * 64;

    const int aRow = tid >> 1;
    const int aCol = (tid & 1) * 16;
    const int bRow = tid >> 4;
    const int bCol = (tid & 15) * 8;

    const __half* Ap = A  + (size_t)blockIdx.y * 128 * K;
    const __half* Bp = Bm + (size_t)blockIdx.x * 128;

    const uint32_t asBase = smem_u32(As);
    const uint32_t bsBase = smem_u32(Bs);
    const uint32_t aDst = asBase + (uint32_t)(aRow * G_SA + aCol) * 2;
    const uint32_t bDst0 = bsBase + (uint32_t)(bRow * G_SB + bCol) * 2;
    const uint32_t bDst1 = bsBase + (uint32_t)((bRow + 16) * G_SB + bCol) * 2;
    const int lrow = lane & 15;
    const int lcb  = (lane >> 4) << 3;

    // issue tile 0
    {
        const __half* Ar = Ap + (size_t)aRow * K + aCol;
        cpa16(aDst,      Ar);
        cpa16(aDst + 16, Ar + 8);
        cpa16(bDst0, Bp + (size_t)bRow        * N + bCol);
        cpa16(bDst1, Bp + (size_t)(bRow + 16) * N + bCol);
        CPA_COMMIT();
    }
    CPA_WAIT0();
    __syncthreads();

    float acc[2][8][4];
    #pragma unroll
    for (int mi = 0; mi < 2; mi++)
        #pragma unroll
        for (int ni = 0; ni < 8; ni++)
            #pragma unroll
            for (int e = 0; e < 4; e++) acc[mi][ni][e] = 0.f;

    const int nT = K / G_BK;
    for (int t = 0; t < nT; t++) {
        const int cur = t & 1;

        if (t + 1 < nT) {
            const uint32_t boff = (uint32_t)((t + 1) & 1);
            const __half* Ar = Ap + (size_t)aRow * K + (t + 1) * G_BK + aCol;
            cpa16(aDst + boff * G_ABUF,      Ar);
            cpa16(aDst + boff * G_ABUF + 16, Ar + 8);
            const __half* Br = Bp + (size_t)((t + 1) * G_BK) * N;
            cpa16(bDst0 + boff * G_BBUF, Br + (size_t)bRow        * N + bCol);
            cpa16(bDst1 + boff * G_BBUF, Br + (size_t)(bRow + 16) * N + bCol);
            CPA_COMMIT();
        }

        const uint32_t asB = asBase + (uint32_t)cur * G_ABUF;
        const uint32_t bsB = bsBase + (uint32_t)cur * G_BBUF;
        #pragma unroll
        for (int ks = 0; ks < G_BK; ks += 16) {
            uint32_t af[2][4];
            ldm_x4(af[0], asB + (uint32_t)((mbase      + lrow) * G_SA + ks + lcb) * 2);
            ldm_x4(af[1], asB + (uint32_t)((mbase + 16 + lrow) * G_SA + ks + lcb) * 2);
            uint32_t bf[8][2];
            #pragma unroll
            for (int nb = 0; nb < 4; nb++) {
                uint32_t td[4];
                ldm_x4_t(td, bsB + (uint32_t)((ks + lrow) * G_SB + nbase + nb * 16 + lcb) * 2);
                bf[2 * nb][0]     = td[0];
                bf[2 * nb][1]     = td[1];
                bf[2 * nb + 1][0] = td[2];
                bf[2 * nb + 1][1] = td[3];
            }
            #pragma unroll
            for (int mi = 0; mi < 2; mi++)
                #pragma unroll
                for (int ni = 0; ni < 8; ni++)
                    mma_f16(acc[mi][ni], af[mi], bf[ni]);
        }

        if (t + 1 < nT) CPA_WAIT0();
        __syncthreads();
    }

    OutT* Cp = C + (size_t)(blockIdx.y * 128 + mbase) * N + blockIdx.x * 128 + nbase;
    #pragma unroll
    for (int mi = 0; mi < 2; mi++) {
        const int r = mi * 16 + (lane >> 2);
        #pragma unroll
        for (int ni = 0; ni < 8; ni++) {
            const int c = ni * 8 + (lane & 3) * 2;
            if constexpr (sizeof(OutT) == 2) {
                *(uint32_t*)(Cp + (size_t)r       * N + c) = f2h2(acc[mi][ni][0], acc[mi][ni][1]);
                *(uint32_t*)(Cp + (size_t)(r + 8) * N + c) = f2h2(acc[mi][ni][2], acc[mi][ni][3]);
            } else {
                *(float2*)(Cp + (size_t)r       * N + c) = make_float2(acc[mi][ni][0], acc[mi][ni][1]);
                *(float2*)(Cp + (size_t)(r + 8) * N + c) = make_float2(acc[mi][ni][2], acc[mi][ni][3]);
            }
        }
    }
}

// ----------------------------------------------------------------------------
// RoPE (in place, fused qkv) using precomputed cos/sin tables.
// ----------------------------------------------------------------------------
__global__ __launch_bounds__(256) void rope2_kernel(
    __half* __restrict__ qkv, const float* __restrict__ ct, const float* __restrict__ st)
{
    const size_t half_n = (size_t)ROWS * HEADS * 64;
    size_t idx = (size_t)blockIdx.x * blockDim.x + threadIdx.x;
    int coff;
    if (idx >= half_n) {
        if (idx >= 2 * half_n) return;
        idx -= half_n;
        coff = INNER;
    } else {
        coff = 0;
    }
    const int d = (int)(idx & 63);
    const int h = (int)((idx >> 6) & (HEADS - 1));
    const int r = (int)(idx >> 10);
    const int n = r & (N_SEQ - 1);

    __half* base = qkv + (size_t)r * NQKV + coff + h * DHEAD;
    const float c1 = ct[n * DHEAD + d];
    const float s1 = st[n * DHEAD + d];
    const float c2 = ct[n * DHEAD + d + 64];
    const float s2 = st[n * DHEAD + d + 64];
    const float t1 = __half2float(base[d]);
    const float t2 = __half2float(base[d + 64]);
    base[d]      = __float2half(t1 * c1 - t2 * s1);
    base[d + 64] = __float2half(t2 * c2 + t1 * s2);
}

// ----------------------------------------------------------------------------
// Causal flash attention, fp16 m16n8k16, fused-qkv input. (unchanged)
// ----------------------------------------------------------------------------
#define FA_BM 128
#define FA_BN 64
#define FA_SK 136

__global__ __launch_bounds__(256, 1) void attn_h16_kernel(
    const __half* __restrict__ QKV, __half* __restrict__ O)
{
    __shared__ __half Ks[FA_BN][FA_SK];
    __shared__ __half Vs[FA_BN][FA_SK];

    const int bh = blockIdx.y;
    const int b  = bh >> 4;
    const int h  = bh & 15;
    const int qt = gridDim.x - 1 - blockIdx.x;

    const int tid  = threadIdx.x;
    const int lane = tid & 31;
    const int warp = tid >> 5;

    const uint32_t ksBase = smem_u32(Ks);
    const uint32_t vsBase = smem_u32(Vs);

    const float qsf = 0.088388347648318447f * 1.4426950408889634f;
    const uint32_t qs2 = f2h2(qsf, qsf);
    uint32_t qf[8][4];
    {
        const __half* qb = QKV + ((size_t)(b * N_SEQ + qt * FA_BM + warp * 16 + (lane >> 2))) * NQKV
                               + h * DHEAD;
        #pragma unroll
        for (int ks = 0; ks < 8; ks++) {
            const int k0 = ks * 16 + 2 * (lane & 3);
            qf[ks][0] = hmul2(*(const uint32_t*)(qb + k0), qs2);
            qf[ks][1] = hmul2(*(const uint32_t*)(qb + 8 * NQKV + k0), qs2);
            qf[ks][2] = hmul2(*(const uint32_t*)(qb + k0 + 8), qs2);
            qf[ks][3] = hmul2(*(const uint32_t*)(qb + 8 * NQKV + k0 + 8), qs2);
        }
    }

    float oacc[16][4];
    #pragma unroll
    for (int nd = 0; nd < 16; nd++)
        #pragma unroll
        for (int e = 0; e < 4; e++) oacc[nd][e] = 0.f;

    float m0 = -INFINITY, m1 = -INFINITY, l0 = 0.f, l1 = 0.f;
    const int qrow0 = qt * FA_BM + warp * 16 + (lane >> 2);
    const int warp_min_row = qt * FA_BM + warp * 16;
    const int warp_max_row = warp_min_row + 15;

    const int ntiles = 2 * qt + 2;
    for (int kt = 0; kt < ntiles; kt++) {
        __syncthreads();
        const __half* kvbase = QKV + ((size_t)(b * N_SEQ + kt * FA_BN)) * NQKV
                                   + INNER + h * DHEAD;
        #pragma unroll
        for (int i = 0; i < 4; i++) {
            const int idx = i * 256 + tid;
            const int r = idx >> 4;
            const int c = (idx & 15) * 8;
            *(uint4*)&Ks[r][c] = *(const uint4*)(kvbase + (size_t)r * NQKV + c);
            *(uint4*)&Vs[r][c] = *(const uint4*)(kvbase + (size_t)r * NQKV + INNER + c);
        }
        __syncthreads();

        if (kt * FA_BN > warp_max_row) continue;

        float sacc[8][4];
        #pragma unroll
        for (int ni = 0; ni < 8; ni++)
            #pragma unroll
            for (int e = 0; e < 4; e++) sacc[ni][e] = 0.f;

        #pragma unroll
        for (int ks = 0; ks < 8; ks++) {
            uint32_t kf[8][2];
            #pragma unroll
            for (int np = 0; np < 4; np++) {
                uint32_t td[4];
                ldm_x4(td, ksBase + (uint32_t)(
                    (np * 16 + (lane & 7) + ((lane >> 4) << 3)) * FA_SK
                    + ks * 16 + (lane & 8)) * 2);
                kf[2 * np][0]     = td[0];
                kf[2 * np][1]     = td[1];
                kf[2 * np + 1][0] = td[2];
                kf[2 * np + 1][1] = td[3];
            }
            #pragma unroll
            for (int ni = 0; ni < 8; ni++)
                mma_f16(sacc[ni], qf[ks], kf[ni]);
        }

        if (kt * FA_BN + FA_BN - 1 > warp_min_row) {
            #pragma unroll
            for (int ni = 0; ni < 8; ni++) {
                const int cg = kt * FA_BN + ni * 8 + 2 * (lane & 3);
                #pragma unroll
                for (int e = 0; e < 4; e++) {
                    const int col = cg + (e & 1);
                    const int row = qrow0 + (e >> 1) * 8;
                    if (col > row) sacc[ni][e] = -INFINITY;
                }
            }
        }

        float rmax0 = -INFINITY, rmax1 = -INFINITY;
        #pragma unroll
        for (int ni = 0; ni < 8; ni++) {
            rmax0 = fmaxf(rmax0, fmaxf(sacc[ni][0], sacc[ni][1]));
            rmax1 = fmaxf(rmax1, fmaxf(sacc[ni][2], sacc[ni][3]));
        }
        rmax0 = fmaxf(rmax0, __shfl_xor_sync(0xffffffffu, rmax0, 1));
        rmax0 = fmaxf(rmax0, __shfl_xor_sync(0xffffffffu, rmax0, 2));
        rmax1 = fmaxf(rmax1, __shfl_xor_sync(0xffffffffu, rmax1, 1));
        rmax1 = fmaxf(rmax1, __shfl_xor_sync(0xffffffffu, rmax1, 2));

        const float mn0 = fmaxf(m0, rmax0);
        const float mn1 = fmaxf(m1, rmax1);
        const float c0 = fex2(m0 - mn0);
        const float c1 = fex2(m1 - mn1);
        float ps0 = 0.f, ps1 = 0.f;
        #pragma unroll
        for (int ni = 0; ni < 8; ni++) {
            sacc[ni][0] = fex2(sacc[ni][0] - mn0);
            sacc[ni][1] = fex2(sacc[ni][1] - mn0);
            sacc[ni][2] = fex2(sacc[ni][2] - mn1);
            sacc[ni][3] = fex2(sacc[ni][3] - mn1);
            ps0 += sacc[ni][0] + sacc[ni][1];
            ps1 += sacc[ni][2] + sacc[ni][3];
        }
        ps0 += __shfl_xor_sync(0xffffffffu, ps0, 1);
        ps0 += __shfl_xor_sync(0xffffffffu, ps0, 2);
        ps1 += __shfl_xor_sync(0xffffffffu, ps1, 1);
        ps1 += __shfl_xor_sync(0xffffffffu, ps1, 2);
        l0 = l0 * c0 + ps0;
        l1 = l1 * c1 + ps1;
        m0 = mn0;
        m1 = mn1;
        #pragma unroll
        for (int nd = 0; nd < 16; nd++) {
            oacc[nd][0] *= c0;
            oacc[nd][1] *= c0;
            oacc[nd][2] *= c1;
            oacc[nd][3] *= c1;
        }

        #pragma unroll
        for (int j = 0; j < 4; j++) {
            uint32_t a[4];
            a[0] = f2h2(sacc[2 * j][0],     sacc[2 * j][1]);
            a[1] = f2h2(sacc[2 * j][2],     sacc[2 * j][3]);
            a[2] = f2h2(sacc[2 * j + 1][0], sacc[2 * j + 1][1]);
            a[3] = f2h2(sacc[2 * j + 1][2], sacc[2 * j + 1][3]);
            #pragma unroll
            for (int np = 0; np < 8; np++) {
                uint32_t v[4];
                ldm_x4_t(v, vsBase + (uint32_t)(
                    (j * 16 + (lane & 15)) * FA_SK
                    + np * 16 + ((lane >> 4) << 3)) * 2);
                mma_f16(oacc[2 * np],     a, v);
                mma_f16(oacc[2 * np + 1], a, v + 2);
            }
        }
    }

    const float inv0 = 1.f / l0;
    const float inv1 = 1.f / l1;
    __half* ob = O + ((size_t)(b * N_SEQ + qt * FA_BM + warp * 16 + (lane >> 2))) * INNER
                   + h * DHEAD + 2 * (lane & 3);
    #pragma unroll
    for (int nd = 0; nd < 16; nd++) {
        *(uint32_t*)(ob + nd * 8) = f2h2(oacc[nd][0] * inv0, oacc[nd][1] * inv0);
        *(uint32_t*)(ob + (size_t)8 * INNER + nd * 8) =
            f2h2(oacc[nd][2] * inv1, oacc[nd][3] * inv1);
    }
}

// ----------------------------------------------------------------------------
// Launch
// ----------------------------------------------------------------------------
extern "C" void kernel_launch(void* const* d_in, const int* in_sizes, int n_in,
                              void* d_out, int out_size)
{
    const float* x   = (const float*)d_in[0];
    const float* re  = (const float*)d_in[1];
    const float* g   = (const float*)d_in[2];
    const float* Wq  = (const float*)d_in[3];
    const float* Wkv = (const float*)d_in[4];
    const float* Wo  = (const float*)d_in[5];
    float* out = (float*)d_out;

    __half *xn, *qkv, *o, *wqkv, *wo;
    float *ct, *st;
    cudaGetSymbolAddress((void**)&xn,   g_xn);
    cudaGetSymbolAddress((void**)&qkv,  g_qkv);
    cudaGetSymbolAddress((void**)&o,    g_o);
    cudaGetSymbolAddress((void**)&wqkv, g_wqkv);
    cudaGetSymbolAddress((void**)&wo,   g_wo);
    cudaGetSymbolAddress((void**)&ct,   g_cos);
    cudaGetSymbolAddress((void**)&st,   g_sin);

    // 0) weight conversion + cos/sin tables
    cvtw_kernel<<<(DIM * INNER / 4 + 255) / 256, 256>>>(
        Wq, wqkv, INNER, NQKV, 0, DIM * INNER);
    cvtw_kernel<<<(DIM * 2 * INNER / 4 + 255) / 256, 256>>>(
        Wkv, wqkv, 2 * INNER, NQKV, INNER, DIM * 2 * INNER);
    cvtw_kernel<<<(INNER * DIM / 4 + 255) / 256, 256>>>(
        Wo, wo, DIM, DIM, 0, INNER * DIM);
    sincos_kernel<<<(N_SEQ * DHEAD + 255) / 256, 256>>>(re, ct, st);

    // 1) RMSNorm (fp16 out)
    rmsnorm_kernel<<<ROWS, 256>>>(x, g, xn);

    // 2) fused qkv projection
    dim3 gp(NQKV / 128, ROWS / 128);
    h16_gemm_kernel<__half><<<gp, 256>>>(ROWS, NQKV, DIM, xn, wqkv, qkv);

    // 3) RoPE (table-based)
    const size_t ropeN = 2 * (size_t)ROWS * HEADS * 64;
    const int ropeBlocks = (int)((ropeN + 255) / 256);
    rope2_kernel<<<ropeBlocks, 256>>>(qkv, ct, st);

    // 4) causal attention
    dim3 ga(N_SEQ / FA_BM, B * HEADS);
    attn_h16_kernel<<<ga, 256>>>(qkv, o);

    // 5) output projection
    dim3 go(DIM / 128, ROWS / 128);
    h16_gemm_kernel<float><<<go, 256>>>(ROWS, DIM, DIM, o, wo, out);
}

// round 14
// speedup vs baseline: 1.0408x; 1.0408x over previous
#include <cuda_runtime.h>
#include <cuda_fp16.h>
#include <math.h>
#include <stdint.h>

// ----------------------------------------------------------------------------
// Problem constants
// ----------------------------------------------------------------------------
#define B      2
#define N_SEQ  2048
#define DIM    2048
#define HEADS  16
#define DHEAD  128
#define INNER  (HEADS * DHEAD)       // 2048
#define ROWS   (B * N_SEQ)           // 4096
#define NQKV   (3 * INNER)           // 6144

// ----------------------------------------------------------------------------
// Scratch (device globals; no allocations allowed)
// ----------------------------------------------------------------------------
__device__ __half g_xn  [ROWS * DIM];
__device__ __half g_qkv [ROWS * NQKV];
__device__ __half g_o   [ROWS * INNER];
__device__ __half g_wqkv[DIM * NQKV];
__device__ __half g_wo  [INNER * DIM];
__device__ float  g_cos [N_SEQ * DHEAD];
__device__ float  g_sin [N_SEQ * DHEAD];

// ----------------------------------------------------------------------------
// helpers
// ----------------------------------------------------------------------------
__device__ __forceinline__ uint32_t f2h2(float lo, float hi) {
    uint32_t r;
    asm("cvt.rn.f16x2.f32 %0, %1, %2;" : "=r"(r) : "f"(hi), "f"(lo));
    return r;
}

__device__ __forceinline__ uint32_t hmul2(uint32_t a, uint32_t b) {
    uint32_t r;
    asm("mul.rn.f16x2 %0, %1, %2;" : "=r"(r) : "r"(a), "r"(b));
    return r;
}

__device__ __forceinline__ float fex2(float x) {
    float y;
    asm("ex2.approx.ftz.f32 %0, %1;" : "=f"(y) : "f"(x));
    return y;
}

__device__ __forceinline__ void mma_f16(float* c, const uint32_t* a, const uint32_t* b) {
    asm volatile(
        "mma.sync.aligned.m16n8k16.row.col.f32.f16.f16.f32 "
        "{%0,%1,%2,%3},{%4,%5,%6,%7},{%8,%9},{%0,%1,%2,%3};"
        : "+f"(c[0]), "+f"(c[1]), "+f"(c[2]), "+f"(c[3])
        : "r"(a[0]), "r"(a[1]), "r"(a[2]), "r"(a[3]), "r"(b[0]), "r"(b[1]));
}

__device__ __forceinline__ void ldm_x4(uint32_t* d, uint32_t addr) {
    asm volatile("ldmatrix.sync.aligned.m8n8.x4.shared.b16 {%0,%1,%2,%3}, [%4];"
                 : "=r"(d[0]), "=r"(d[1]), "=r"(d[2]), "=r"(d[3]) : "r"(addr));
}
__device__ __forceinline__ void ldm_x4_t(uint32_t* d, uint32_t addr) {
    asm volatile("ldmatrix.sync.aligned.m8n8.x4.trans.shared.b16 {%0,%1,%2,%3}, [%4];"
                 : "=r"(d[0]), "=r"(d[1]), "=r"(d[2]), "=r"(d[3]) : "r"(addr));
}

__device__ __forceinline__ uint32_t smem_u32(const void* p) {
    uint32_t a;
    asm("{ .reg .u64 t; cvta.to.shared.u64 t, %1; cvt.u32.u64 %0, t; }"
        : "=r"(a) : "l"(p));
    return a;
}

__device__ __forceinline__ void cpa16(uint32_t saddr, const void* g) {
    asm volatile("cp.async.cg.shared.global [%0], [%1], 16;" :: "r"(saddr), "l"(g));
}
#define CPA_COMMIT() asm volatile("cp.async.commit_group;" ::: "memory")
#define CPA_WAIT0()  asm volatile("cp.async.wait_group 0;"  ::: "memory")

// ----------------------------------------------------------------------------
// Weight fp32 -> fp16 conversion (with column remap into fused buffers)
// ----------------------------------------------------------------------------
__global__ __launch_bounds__(256) void cvtw_kernel(
    const float* __restrict__ src, __half* __restrict__ dst,
    int src_ncols, int dst_ncols, int col_off, int n)
{
    const int idx = (blockIdx.x * 256 + threadIdx.x) * 4;
    if (idx >= n) return;
    const int r = idx / src_ncols;
    const int c = idx - r * src_ncols;
    float4 v = *(const float4*)(src + idx);
    *(uint2*)(dst + (size_t)r * dst_ncols + col_off + c) =
        make_uint2(f2h2(v.x, v.y), f2h2(v.z, v.w));
}

// ----------------------------------------------------------------------------
// cos/sin table precompute
// ----------------------------------------------------------------------------
__global__ __launch_bounds__(256) void sincos_kernel(
    const float* __restrict__ re, float* __restrict__ ct, float* __restrict__ st)
{
    const int i = blockIdx.x * 256 + threadIdx.x;
    if (i < N_SEQ * DHEAD) {
        const float p = re[i];
        ct[i] = cosf(p);
        st[i] = sinf(p);
    }
}

// ----------------------------------------------------------------------------
// RMSNorm -> fp16 output (float4 path)
// ----------------------------------------------------------------------------
__global__ __launch_bounds__(256) void rmsnorm_kernel(
    const float* __restrict__ x, const float* __restrict__ g,
    __half* __restrict__ xn)
{
    const int row = blockIdx.x;
    const float* xr = x  + (size_t)row * DIM;
    __half*      xo = xn + (size_t)row * DIM;

    float ss = 0.f;
    #pragma unroll
    for (int i = threadIdx.x * 4; i < DIM; i += 1024) {
        float4 v = *(const float4*)(xr + i);
        ss += v.x * v.x + v.y * v.y + v.z * v.z + v.w * v.w;
    }
    __shared__ float red[8];
    #pragma unroll
    for (int o = 16; o > 0; o >>= 1) ss += __shfl_xor_sync(0xffffffffu, ss, o);
    if ((threadIdx.x & 31) == 0) red[threadIdx.x >> 5] = ss;
    __syncthreads();
    if (threadIdx.x < 8) {
        float v = red[threadIdx.x];
        #pragma unroll
        for (int o = 4; o > 0; o >>= 1) v += __shfl_xor_sync(0x000000ffu, v, o);
        if (threadIdx.x == 0) red[0] = v;
    }
    __syncthreads();
    const float rms = sqrtf(red[0] * (1.f / (float)DIM));
    const float inv = 1.f / fmaxf(rms, 1e-8f);
    #pragma unroll
    for (int i = threadIdx.x * 4; i < DIM; i += 1024) {
        float4 v = *(const float4*)(xr + i);
        float4 gg = *(const float4*)(g + i);
        *(uint2*)(xo + i) = make_uint2(
            f2h2(v.x * inv * gg.x, v.y * inv * gg.y),
            f2h2(v.z * inv * gg.z, v.w * inv * gg.w));
    }
}

// ----------------------------------------------------------------------------
// FP16 tensor-core GEMM (m16n8k16), cp.async double-buffered, ldmatrix.
// ----------------------------------------------------------------------------
#define G_BK 32
#define G_SA 40
#define G_SB 136
#define G_ABUF (128 * G_SA * 2)
#define G_BBUF (G_BK * G_SB * 2)

template <typename OutT>
__global__ __launch_bounds__(256, 2) void h16_gemm_kernel(
    int M, int N, int K,
    const __half* __restrict__ A, const __half* __restrict__ Bm,
    OutT* __restrict__ C)
{
    __shared__ __half As[2][128][G_SA];
    __shared__ __half Bs[2][G_BK][G_SB];

    const int tid  = threadIdx.x;
    const int lane = tid & 31;
    const int warp = tid >> 5;
    const int mbase = (warp >> 1) * 32;
    const int nbase = (warp & 1) * 64;

    const int aRow = tid >> 1;
    const int aCol = (tid & 1) * 16;
    const int bRow = tid >> 4;
    const int bCol = (tid & 15) * 8;

    const __half* Ap = A  + (size_t)blockIdx.y * 128 * K;
    const __half* Bp = Bm + (size_t)blockIdx.x * 128;

    const uint32_t asBase = smem_u32(As);
    const uint32_t bsBase = smem_u32(Bs);
    const uint32_t aDst = asBase + (uint32_t)(aRow * G_SA + aCol) * 2;
    const uint32_t bDst0 = bsBase + (uint32_t)(bRow * G_SB + bCol) * 2;
    const uint32_t bDst1 = bsBase + (uint32_t)((bRow + 16) * G_SB + bCol) * 2;
    const int lrow = lane & 15;
    const int lcb  = (lane >> 4) << 3;

    {
        const __half* Ar = Ap + (size_t)aRow * K + aCol;
        cpa16(aDst,      Ar);
        cpa16(aDst + 16, Ar + 8);
        cpa16(bDst0, Bp + (size_t)bRow        * N + bCol);
        cpa16(bDst1, Bp + (size_t)(bRow + 16) * N + bCol);
        CPA_COMMIT();
    }
    CPA_WAIT0();
    __syncthreads();

    float acc[2][8][4];
    #pragma unroll
    for (int mi = 0; mi < 2; mi++)
        #pragma unroll
        for (int ni = 0; ni < 8; ni++)
            #pragma unroll
            for (int e = 0; e < 4; e++) acc[mi][ni][e] = 0.f;

    const int nT = K / G_BK;
    for (int t = 0; t < nT; t++) {
        const int cur = t & 1;

        if (t + 1 < nT) {
            const uint32_t boff = (uint32_t)((t + 1) & 1);
            const __half* Ar = Ap + (size_t)aRow * K + (t + 1) * G_BK + aCol;
            cpa16(aDst + boff * G_ABUF,      Ar);
            cpa16(aDst + boff * G_ABUF + 16, Ar + 8);
            const __half* Br = Bp + (size_t)((t + 1) * G_BK) * N;
            cpa16(bDst0 + boff * G_BBUF, Br + (size_t)bRow        * N + bCol);
            cpa16(bDst1 + boff * G_BBUF, Br + (size_t)(bRow + 16) * N + bCol);
            CPA_COMMIT();
        }

        const uint32_t asB = asBase + (uint32_t)cur * G_ABUF;
        const uint32_t bsB = bsBase + (uint32_t)cur * G_BBUF;
        #pragma unroll
        for (int ks = 0; ks < G_BK; ks += 16) {
            uint32_t af[2][4];
            ldm_x4(af[0], asB + (uint32_t)((mbase      + lrow) * G_SA + ks + lcb) * 2);
            ldm_x4(af[1], asB + (uint32_t)((mbase + 16 + lrow) * G_SA + ks + lcb) * 2);
            uint32_t bf[8][2];
            #pragma unroll
            for (int nb = 0; nb < 4; nb++) {
                uint32_t td[4];
                ldm_x4_t(td, bsB + (uint32_t)((ks + lrow) * G_SB + nbase + nb * 16 + lcb) * 2);
                bf[2 * nb][0]     = td[0];
                bf[2 * nb][1]     = td[1];
                bf[2 * nb + 1][0] = td[2];
                bf[2 * nb + 1][1] = td[3];
            }
            #pragma unroll
            for (int mi = 0; mi < 2; mi++)
                #pragma unroll
                for (int ni = 0; ni < 8; ni++)
                    mma_f16(acc[mi][ni], af[mi], bf[ni]);
        }

        if (t + 1 < nT) CPA_WAIT0();
        __syncthreads();
    }

    OutT* Cp = C + (size_t)(blockIdx.y * 128 + mbase) * N + blockIdx.x * 128 + nbase;
    #pragma unroll
    for (int mi = 0; mi < 2; mi++) {
        const int r = mi * 16 + (lane >> 2);
        #pragma unroll
        for (int ni = 0; ni < 8; ni++) {
            const int c = ni * 8 + (lane & 3) * 2;
            if constexpr (sizeof(OutT) == 2) {
                *(uint32_t*)(Cp + (size_t)r       * N + c) = f2h2(acc[mi][ni][0], acc[mi][ni][1]);
                *(uint32_t*)(Cp + (size_t)(r + 8) * N + c) = f2h2(acc[mi][ni][2], acc[mi][ni][3]);
            } else {
                *(float2*)(Cp + (size_t)r       * N + c) = make_float2(acc[mi][ni][0], acc[mi][ni][1]);
                *(float2*)(Cp + (size_t)(r + 8) * N + c) = make_float2(acc[mi][ni][2], acc[mi][ni][3]);
            }
        }
    }
}

// ----------------------------------------------------------------------------
// RoPE (in place, fused qkv) using precomputed cos/sin tables.
// ----------------------------------------------------------------------------
__global__ __launch_bounds__(256) void rope2_kernel(
    __half* __restrict__ qkv, const float* __restrict__ ct, const float* __restrict__ st)
{
    const size_t half_n = (size_t)ROWS * HEADS * 64;
    size_t idx = (size_t)blockIdx.x * blockDim.x + threadIdx.x;
    int coff;
    if (idx >= half_n) {
        if (idx >= 2 * half_n) return;
        idx -= half_n;
        coff = INNER;
    } else {
        coff = 0;
    }
    const int d = (int)(idx & 63);
    const int h = (int)((idx >> 6) & (HEADS - 1));
    const int r = (int)(idx >> 10);
    const int n = r & (N_SEQ - 1);

    __half* base = qkv + (size_t)r * NQKV + coff + h * DHEAD;
    const float c1 = ct[n * DHEAD + d];
    const float s1 = st[n * DHEAD + d];
    const float c2 = ct[n * DHEAD + d + 64];
    const float s2 = st[n * DHEAD + d + 64];
    const float t1 = __half2float(base[d]);
    const float t2 = __half2float(base[d + 64]);
    base[d]      = __float2half(t1 * c1 - t2 * s1);
    base[d + 64] = __float2half(t2 * c2 + t1 * s2);
}

// ----------------------------------------------------------------------------
// Causal flash attention, fp16 m16n8k16, cp.async double-buffered KV.
// Dynamic smem: 2 stages x (K tile + V tile), each [64][136] halfs.
// ----------------------------------------------------------------------------
#define FA_BM 128
#define FA_BN 64
#define FA_SK 136
#define FA_KVST (2 * FA_BN * FA_SK)                 // halfs per stage (K+V)
#define FA_SMEM (2 * FA_KVST * 2)                   // bytes total (2 stages)

__global__ __launch_bounds__(256, 1) void attn_h16_kernel(
    const __half* __restrict__ QKV, __half* __restrict__ O)
{
    extern __shared__ __half smh[];
    const uint32_t sBase = smem_u32(smh);

    const int bh = blockIdx.y;
    const int b  = bh >> 4;
    const int h  = bh & 15;
    const int qt = gridDim.x - 1 - blockIdx.x;

    const int tid  = threadIdx.x;
    const int lane = tid & 31;
    const int warp = tid >> 5;

    // per-thread KV copy coords: 4 rows x 16B for K, same for V
    const int cr = tid >> 4;              // 0..15 (rows cr, cr+16, cr+32, cr+48)
    const int cc = (tid & 15) * 8;        // 0..120
    const __half* kvb = QKV + ((size_t)(b * N_SEQ)) * NQKV + INNER + h * DHEAD;

    // issue tile 0 loads
    {
        const __half* kv0 = kvb;
        #pragma unroll
        for (int i = 0; i < 4; i++) {
            const int r = i * 16 + cr;
            const uint32_t kD = sBase + (uint32_t)(r * FA_SK + cc) * 2;
            cpa16(kD, kv0 + (size_t)r * NQKV + cc);
            cpa16(kD + FA_BN * FA_SK * 2, kv0 + (size_t)r * NQKV + INNER + cc);
        }
        CPA_COMMIT();
    }

    // Q fragments (overlap with tile-0 loads)
    const float qsf = 0.088388347648318447f * 1.4426950408889634f;
    const uint32_t qs2 = f2h2(qsf, qsf);
    uint32_t qf[8][4];
    {
        const __half* qb = QKV + ((size_t)(b * N_SEQ + qt * FA_BM + warp * 16 + (lane >> 2))) * NQKV
                               + h * DHEAD;
        #pragma unroll
        for (int ks = 0; ks < 8; ks++) {
            const int k0 = ks * 16 + 2 * (lane & 3);
            qf[ks][0] = hmul2(*(const uint32_t*)(qb + k0), qs2);
            qf[ks][1] = hmul2(*(const uint32_t*)(qb + 8 * NQKV + k0), qs2);
            qf[ks][2] = hmul2(*(const uint32_t*)(qb + k0 + 8), qs2);
            qf[ks][3] = hmul2(*(const uint32_t*)(qb + 8 * NQKV + k0 + 8), qs2);
        }
    }

    float oacc[16][4];
    #pragma unroll
    for (int nd = 0; nd < 16; nd++)
        #pragma unroll
        for (int e = 0; e < 4; e++) oacc[nd][e] = 0.f;

    float m0 = -INFINITY, m1 = -INFINITY, l0 = 0.f, l1 = 0.f;
    const int qrow0 = qt * FA_BM + warp * 16 + (lane >> 2);
    const int warp_min_row = qt * FA_BM + warp * 16;
    const int warp_max_row = warp_min_row + 15;

    CPA_WAIT0();
    __syncthreads();

    const int ntiles = 2 * qt + 2;
    for (int kt = 0; kt < ntiles; kt++) {
        const int cur = kt & 1;

        // issue loads for tile kt+1 into the other stage
        if (kt + 1 < ntiles) {
            const int nxt = cur ^ 1;
            const __half* kvn = kvb + (size_t)((kt + 1) * FA_BN) * NQKV;
            const uint32_t stB = sBase + (uint32_t)nxt * FA_KVST * 2;
            #pragma unroll
            for (int i = 0; i < 4; i++) {
                const int r = i * 16 + cr;
                const uint32_t kD = stB + (uint32_t)(r * FA_SK + cc) * 2;
                cpa16(kD, kvn + (size_t)r * NQKV + cc);
                cpa16(kD + FA_BN * FA_SK * 2, kvn + (size_t)r * NQKV + INNER + cc);
            }
            CPA_COMMIT();
        }

        if (kt * FA_BN <= warp_max_row) {
            const uint32_t ksBase = sBase + (uint32_t)cur * FA_KVST * 2;
            const uint32_t vsBase = ksBase + FA_BN * FA_SK * 2;

            // ---- S = Q @ K^T ---------------------------------------------
            float sacc[8][4];
            #pragma unroll
            for (int ni = 0; ni < 8; ni++)
                #pragma unroll
                for (int e = 0; e < 4; e++) sacc[ni][e] = 0.f;

            #pragma unroll
            for (int ks = 0; ks < 8; ks++) {
                uint32_t kf[8][2];
                #pragma unroll
                for (int np = 0; np < 4; np++) {
                    uint32_t td[4];
                    ldm_x4(td, ksBase + (uint32_t)(
                        (np * 16 + (lane & 7) + ((lane >> 4) << 3)) * FA_SK
                        + ks * 16 + (lane & 8)) * 2);
                    kf[2 * np][0]     = td[0];
                    kf[2 * np][1]     = td[1];
                    kf[2 * np + 1][0] = td[2];
                    kf[2 * np + 1][1] = td[3];
                }
                #pragma unroll
                for (int ni = 0; ni < 8; ni++)
                    mma_f16(sacc[ni], qf[ks], kf[ni]);
            }

            // ---- causal mask (diagonal tiles only) -----------------------
            if (kt * FA_BN + FA_BN - 1 > warp_min_row) {
                #pragma unroll
                for (int ni = 0; ni < 8; ni++) {
                    const int cg = kt * FA_BN + ni * 8 + 2 * (lane & 3);
                    #pragma unroll
                    for (int e = 0; e < 4; e++) {
                        const int col = cg + (e & 1);
                        const int row = qrow0 + (e >> 1) * 8;
                        if (col > row) sacc[ni][e] = -INFINITY;
                    }
                }
            }

            // ---- online softmax (exp2 domain) ----------------------------
            float rmax0 = -INFINITY, rmax1 = -INFINITY;
            #pragma unroll
            for (int ni = 0; ni < 8; ni++) {
                rmax0 = fmaxf(rmax0, fmaxf(sacc[ni][0], sacc[ni][1]));
                rmax1 = fmaxf(rmax1, fmaxf(sacc[ni][2], sacc[ni][3]));
            }
            rmax0 = fmaxf(rmax0, __shfl_xor_sync(0xffffffffu, rmax0, 1));
            rmax0 = fmaxf(rmax0, __shfl_xor_sync(0xffffffffu, rmax0, 2));
            rmax1 = fmaxf(rmax1, __shfl_xor_sync(0xffffffffu, rmax1, 1));
            rmax1 = fmaxf(rmax1, __shfl_xor_sync(0xffffffffu, rmax1, 2));

            const float mn0 = fmaxf(m0, rmax0);
            const float mn1 = fmaxf(m1, rmax1);
            const float c0 = fex2(m0 - mn0);
            const float c1 = fex2(m1 - mn1);
            float ps0 = 0.f, ps1 = 0.f;
            #pragma unroll
            for (int ni = 0; ni < 8; ni++) {
                sacc[ni][0] = fex2(sacc[ni][0] - mn0);
                sacc[ni][1] = fex2(sacc[ni][1] - mn0);
                sacc[ni][2] = fex2(sacc[ni][2] - mn1);
                sacc[ni][3] = fex2(sacc[ni][3] - mn1);
                ps0 += sacc[ni][0] + sacc[ni][1];
                ps1 += sacc[ni][2] + sacc[ni][3];
            }
            ps0 += __shfl_xor_sync(0xffffffffu, ps0, 1);
            ps0 += __shfl_xor_sync(0xffffffffu, ps0, 2);
            ps1 += __shfl_xor_sync(0xffffffffu, ps1, 1);
            ps1 += __shfl_xor_sync(0xffffffffu, ps1, 2);
            l0 = l0 * c0 + ps0;
            l1 = l1 * c1 + ps1;
            m0 = mn0;
            m1 = mn1;
            #pragma unroll
            for (int nd = 0; nd < 16; nd++) {
                oacc[nd][0] *= c0;
                oacc[nd][1] *= c0;
                oacc[nd][2] *= c1;
                oacc[nd][3] *= c1;
            }

            // ---- O += P @ V  (C-frag == A-frag layout) -------------------
            #pragma unroll
            for (int j = 0; j < 4; j++) {
                uint32_t a[4];
                a[0] = f2h2(sacc[2 * j][0],     sacc[2 * j][1]);
                a[1] = f2h2(sacc[2 * j][2],     sacc[2 * j][3]);
                a[2] = f2h2(sacc[2 * j + 1][0], sacc[2 * j + 1][1]);
                a[3] = f2h2(sacc[2 * j + 1][2], sacc[2 * j + 1][3]);
                #pragma unroll
                for (int np = 0; np < 8; np++) {
                    uint32_t v[4];
                    ldm_x4_t(v, vsBase + (uint32_t)(
                        (j * 16 + (lane & 15)) * FA_SK
                        + np * 16 + ((lane >> 4) << 3)) * 2);
                    mma_f16(oacc[2 * np],     a, v);
                    mma_f16(oacc[2 * np + 1], a, v + 2);
                }
            }
        }

        if (kt + 1 < ntiles) CPA_WAIT0();
        __syncthreads();
    }

    // epilogue (fp16 out)
    const float inv0 = 1.f / l0;
    const float inv1 = 1.f / l1;
    __half* ob = O + ((size_t)(b * N_SEQ + qt * FA_BM + warp * 16 + (lane >> 2))) * INNER
                   + h * DHEAD + 2 * (lane & 3);
    #pragma unroll
    for (int nd = 0; nd < 16; nd++) {
        *(uint32_t*)(ob + nd * 8) = f2h2(oacc[nd][0] * inv0, oacc[nd][1] * inv0);
        *(uint32_t*)(ob + (size_t)8 * INNER + nd * 8) =
            f2h2(oacc[nd][2] * inv1, oacc[nd][3] * inv1);
    }
}

// ----------------------------------------------------------------------------
// Launch
// ----------------------------------------------------------------------------
extern "C" void kernel_launch(void* const* d_in, const int* in_sizes, int n_in,
                              void* d_out, int out_size)
{
    const float* x   = (const float*)d_in[0];
    const float* re  = (const float*)d_in[1];
    const float* g   = (const float*)d_in[2];
    const float* Wq  = (const float*)d_in[3];
    const float* Wkv = (const float*)d_in[4];
    const float* Wo  = (const float*)d_in[5];
    float* out = (float*)d_out;

    __half *xn, *qkv, *o, *wqkv, *wo;
    float *ct, *st;
    cudaGetSymbolAddress((void**)&xn,   g_xn);
    cudaGetSymbolAddress((void**)&qkv,  g_qkv);
    cudaGetSymbolAddress((void**)&o,    g_o);
    cudaGetSymbolAddress((void**)&wqkv, g_wqkv);
    cudaGetSymbolAddress((void**)&wo,   g_wo);
    cudaGetSymbolAddress((void**)&ct,   g_cos);
    cudaGetSymbolAddress((void**)&st,   g_sin);

    // 0) weight conversion + cos/sin tables
    cvtw_kernel<<<(DIM * INNER / 4 + 255) / 256, 256>>>(
        Wq, wqkv, INNER, NQKV, 0, DIM * INNER);
    cvtw_kernel<<<(DIM * 2 * INNER / 4 + 255) / 256, 256>>>(
        Wkv, wqkv, 2 * INNER, NQKV, INNER, DIM * 2 * INNER);
    cvtw_kernel<<<(INNER * DIM / 4 + 255) / 256, 256>>>(
        Wo, wo, DIM, DIM, 0, INNER * DIM);
    sincos_kernel<<<(N_SEQ * DHEAD + 255) / 256, 256>>>(re, ct, st);

    // 1) RMSNorm
    rmsnorm_kernel<<<ROWS, 256>>>(x, g, xn);

    // 2) fused qkv projection
    dim3 gp(NQKV / 128, ROWS / 128);
    h16_gemm_kernel<__half><<<gp, 256>>>(ROWS, NQKV, DIM, xn, wqkv, qkv);

    // 3) RoPE (table-based)
    const size_t ropeN = 2 * (size_t)ROWS * HEADS * 64;
    const int ropeBlocks = (int)((ropeN + 255) / 256);
    rope2_kernel<<<ropeBlocks, 256>>>(qkv, ct, st);

    // 4) causal attention (cp.async double-buffered KV)
    cudaFuncSetAttribute(attn_h16_kernel,
                         cudaFuncAttributeMaxDynamicSharedMemorySize, FA_SMEM);
    dim3 ga(N_SEQ / FA_BM, B * HEADS);
    attn_h16_kernel<<<ga, 256, FA_SMEM>>>(qkv, o);

    // 5) output projection
    dim3 go(DIM / 128, ROWS / 128);
    h16_gemm_kernel<float><<<go, 256>>>(ROWS, DIM, DIM, o, wo, out);
}

// round 16
// speedup vs baseline: 1.0619x; 1.0203x over previous
#include <cuda_runtime.h>
#include <cuda_fp16.h>
#include <math.h>
#include <stdint.h>

// ----------------------------------------------------------------------------
// Problem constants
// ----------------------------------------------------------------------------
#define B      2
#define N_SEQ  2048
#define DIM    2048
#define HEADS  16
#define DHEAD  128
#define INNER  (HEADS * DHEAD)       // 2048
#define ROWS   (B * N_SEQ)           // 4096
#define NQKV   (3 * INNER)           // 6144

// ----------------------------------------------------------------------------
// Scratch (device globals; no allocations allowed)
// ----------------------------------------------------------------------------
__device__ __half g_xn  [ROWS * DIM];
__device__ __half g_qkv [ROWS * NQKV];
__device__ __half g_o   [ROWS * INNER];
__device__ __half g_wqkv[DIM * NQKV];
__device__ __half g_wo  [INNER * DIM];
__device__ float  g_cos [N_SEQ * DHEAD];
__device__ float  g_sin [N_SEQ * DHEAD];

// ----------------------------------------------------------------------------
// helpers
// ----------------------------------------------------------------------------
__device__ __forceinline__ uint32_t f2h2(float lo, float hi) {
    uint32_t r;
    asm("cvt.rn.f16x2.f32 %0, %1, %2;" : "=r"(r) : "f"(hi), "f"(lo));
    return r;
}

__device__ __forceinline__ uint32_t hmul2(uint32_t a, uint32_t b) {
    uint32_t r;
    asm("mul.rn.f16x2 %0, %1, %2;" : "=r"(r) : "r"(a), "r"(b));
    return r;
}

__device__ __forceinline__ float fex2(float x) {
    float y;
    asm("ex2.approx.ftz.f32 %0, %1;" : "=f"(y) : "f"(x));
    return y;
}

__device__ __forceinline__ void mma_f16(float* c, const uint32_t* a, const uint32_t* b) {
    asm volatile(
        "mma.sync.aligned.m16n8k16.row.col.f32.f16.f16.f32 "
        "{%0,%1,%2,%3},{%4,%5,%6,%7},{%8,%9},{%0,%1,%2,%3};"
        : "+f"(c[0]), "+f"(c[1]), "+f"(c[2]), "+f"(c[3])
        : "r"(a[0]), "r"(a[1]), "r"(a[2]), "r"(a[3]), "r"(b[0]), "r"(b[1]));
}

__device__ __forceinline__ void ldm_x4(uint32_t* d, uint32_t addr) {
    asm volatile("ldmatrix.sync.aligned.m8n8.x4.shared.b16 {%0,%1,%2,%3}, [%4];"
                 : "=r"(d[0]), "=r"(d[1]), "=r"(d[2]), "=r"(d[3]) : "r"(addr));
}
__device__ __forceinline__ void ldm_x4_t(uint32_t* d, uint32_t addr) {
    asm volatile("ldmatrix.sync.aligned.m8n8.x4.trans.shared.b16 {%0,%1,%2,%3}, [%4];"
                 : "=r"(d[0]), "=r"(d[1]), "=r"(d[2]), "=r"(d[3]) : "r"(addr));
}

__device__ __forceinline__ uint32_t smem_u32(const void* p) {
    uint32_t a;
    asm("{ .reg .u64 t; cvta.to.shared.u64 t, %1; cvt.u32.u64 %0, t; }"
        : "=r"(a) : "l"(p));
    return a;
}

__device__ __forceinline__ void cpa16(uint32_t saddr, const void* g) {
    asm volatile("cp.async.cg.shared.global [%0], [%1], 16;" :: "r"(saddr), "l"(g));
}
#define CPA_COMMIT() asm volatile("cp.async.commit_group;" ::: "memory")
#define CPA_WAIT0()  asm volatile("cp.async.wait_group 0;"  ::: "memory")

// ----------------------------------------------------------------------------
// Fused setup: Wq|Wkv|Wo fp32->fp16 (with remap) + cos/sin tables, one launch.
// ----------------------------------------------------------------------------
#define SU_N0 (DIM * INNER / 4)
#define SU_N1 (DIM * 2 * INNER / 4)
#define SU_N2 (INNER * DIM / 4)
#define SU_N3 (N_SEQ * DHEAD / 4)
#define SU_TOTAL (SU_N0 + SU_N1 + SU_N2 + SU_N3)

__global__ __launch_bounds__(256) void setup_kernel(
    const float* __restrict__ Wq, const float* __restrict__ Wkv,
    const float* __restrict__ Wo, const float* __restrict__ re,
    __half* __restrict__ wqkv, __half* __restrict__ wo,
    float* __restrict__ ct, float* __restrict__ st)
{
    int idx = blockIdx.x * 256 + threadIdx.x;
    if (idx < SU_N0) {
        const int e = idx * 4;
        const int r = e / INNER, c = e - r * INNER;
        float4 v = *(const float4*)(Wq + e);
        *(uint2*)(wqkv + (size_t)r * NQKV + c) =
            make_uint2(f2h2(v.x, v.y), f2h2(v.z, v.w));
        return;
    }
    idx -= SU_N0;
    if (idx < SU_N1) {
        const int e = idx * 4;
        const int r = e / (2 * INNER), c = e - r * (2 * INNER);
        float4 v = *(const float4*)(Wkv + e);
        *(uint2*)(wqkv + (size_t)r * NQKV + INNER + c) =
            make_uint2(f2h2(v.x, v.y), f2h2(v.z, v.w));
        return;
    }
    idx -= SU_N1;
    if (idx < SU_N2) {
        const int e = idx * 4;
        float4 v = *(const float4*)(Wo + e);
        *(uint2*)(wo + e) = make_uint2(f2h2(v.x, v.y), f2h2(v.z, v.w));
        return;
    }
    idx -= SU_N2;
    if (idx < SU_N3) {
        const int e = idx * 4;
        float4 p = *(const float4*)(re + e);
        *(float4*)(ct + e) = make_float4(cosf(p.x), cosf(p.y), cosf(p.z), cosf(p.w));
        *(float4*)(st + e) = make_float4(sinf(p.x), sinf(p.y), sinf(p.z), sinf(p.w));
    }
}

// ----------------------------------------------------------------------------
// RMSNorm -> fp16 output (float4 path)
// ----------------------------------------------------------------------------
__global__ __launch_bounds__(256) void rmsnorm_kernel(
    const float* __restrict__ x, const float* __restrict__ g,
    __half* __restrict__ xn)
{
    const int row = blockIdx.x;
    const float* xr = x  + (size_t)row * DIM;
    __half*      xo = xn + (size_t)row * DIM;

    float ss = 0.f;
    #pragma unroll
    for (int i = threadIdx.x * 4; i < DIM; i += 1024) {
        float4 v = *(const float4*)(xr + i);
        ss += v.x * v.x + v.y * v.y + v.z * v.z + v.w * v.w;
    }
    __shared__ float red[8];
    #pragma unroll
    for (int o = 16; o > 0; o >>= 1) ss += __shfl_xor_sync(0xffffffffu, ss, o);
    if ((threadIdx.x & 31) == 0) red[threadIdx.x >> 5] = ss;
    __syncthreads();
    if (threadIdx.x < 8) {
        float v = red[threadIdx.x];
        #pragma unroll
        for (int o = 4; o > 0; o >>= 1) v += __shfl_xor_sync(0x000000ffu, v, o);
        if (threadIdx.x == 0) red[0] = v;
    }
    __syncthreads();
    const float rms = sqrtf(red[0] * (1.f / (float)DIM));
    const float inv = 1.f / fmaxf(rms, 1e-8f);
    #pragma unroll
    for (int i = threadIdx.x * 4; i < DIM; i += 1024) {
        float4 v = *(const float4*)(xr + i);
        float4 gg = *(const float4*)(g + i);
        *(uint2*)(xo + i) = make_uint2(
            f2h2(v.x * inv * gg.x, v.y * inv * gg.y),
            f2h2(v.z * inv * gg.z, v.w * inv * gg.w));
    }
}

// ----------------------------------------------------------------------------
// FP16 tensor-core GEMM (m16n8k16), cp.async double-buffered, ldmatrix.
// ----------------------------------------------------------------------------
#define G_BK 32
#define G_SA 40
#define G_SB 136
#define G_ABUF (128 * G_SA * 2)
#define G_BBUF (G_BK * G_SB * 2)

template <typename OutT>
__global__ __launch_bounds__(256, 2) void h16_gemm_kernel(
    int M, int N, int K,
    const __half* __restrict__ A, const __half* __restrict__ Bm,
    OutT* __restrict__ C)
{
    __shared__ __half As[2][128][G_SA];
    __shared__ __half Bs[2][G_BK][G_SB];

    const int tid  = threadIdx.x;
    const int lane = tid & 31;
    const int warp = tid >> 5;
    const int mbase = (warp >> 1) * 32;
    const int nbase = (warp & 1) * 64;

    const int aRow = tid >> 1;
    const int aCol = (tid & 1) * 16;
    const int bRow = tid >> 4;
    const int bCol = (tid & 15) * 8;

    const __half* Ap = A  + (size_t)blockIdx.y * 128 * K;
    const __half* Bp = Bm + (size_t)blockIdx.x * 128;

    const uint32_t asBase = smem_u32(As);
    const uint32_t bsBase = smem_u32(Bs);
    const uint32_t aDst = asBase + (uint32_t)(aRow * G_SA + aCol) * 2;
    const uint32_t bDst0 = bsBase + (uint32_t)(bRow * G_SB + bCol) * 2;
    const uint32_t bDst1 = bsBase + (uint32_t)((bRow + 16) * G_SB + bCol) * 2;
    const int lrow = lane & 15;
    const int lcb  = (lane >> 4) << 3;

    {
        const __half* Ar = Ap + (size_t)aRow * K + aCol;
        cpa16(aDst,      Ar);
        cpa16(aDst + 16, Ar + 8);
        cpa16(bDst0, Bp + (size_t)bRow        * N + bCol);
        cpa16(bDst1, Bp + (size_t)(bRow + 16) * N + bCol);
        CPA_COMMIT();
    }
    CPA_WAIT0();
    __syncthreads();

    float acc[2][8][4];
    #pragma unroll
    for (int mi = 0; mi < 2; mi++)
        #pragma unroll
        for (int ni = 0; ni < 8; ni++)
            #pragma unroll
            for (int e = 0; e < 4; e++) acc[mi][ni][e] = 0.f;

    const int nT = K / G_BK;
    for (int t = 0; t < nT; t++) {
        const int cur = t & 1;

        if (t + 1 < nT) {
            const uint32_t boff = (uint32_t)((t + 1) & 1);
            const __half* Ar = Ap + (size_t)aRow * K + (t + 1) * G_BK + aCol;
            cpa16(aDst + boff * G_ABUF,      Ar);
            cpa16(aDst + boff * G_ABUF + 16, Ar + 8);
            const __half* Br = Bp + (size_t)((t + 1) * G_BK) * N;
            cpa16(bDst0 + boff * G_BBUF, Br + (size_t)bRow        * N + bCol);
            cpa16(bDst1 + boff * G_BBUF, Br + (size_t)(bRow + 16) * N + bCol);
            CPA_COMMIT();
        }

        const uint32_t asB = asBase + (uint32_t)cur * G_ABUF;
        const uint32_t bsB = bsBase + (uint32_t)cur * G_BBUF;
        #pragma unroll
        for (int ks = 0; ks < G_BK; ks += 16) {
            uint32_t af[2][4];
            ldm_x4(af[0], asB + (uint32_t)((mbase      + lrow) * G_SA + ks + lcb) * 2);
            ldm_x4(af[1], asB + (uint32_t)((mbase + 16 + lrow) * G_SA + ks + lcb) * 2);
            uint32_t bf[8][2];
            #pragma unroll
            for (int nb = 0; nb < 4; nb++) {
                uint32_t td[4];
                ldm_x4_t(td, bsB + (uint32_t)((ks + lrow) * G_SB + nbase + nb * 16 + lcb) * 2);
                bf[2 * nb][0]     = td[0];
                bf[2 * nb][1]     = td[1];
                bf[2 * nb + 1][0] = td[2];
                bf[2 * nb + 1][1] = td[3];
            }
            #pragma unroll
            for (int mi = 0; mi < 2; mi++)
                #pragma unroll
                for (int ni = 0; ni < 8; ni++)
                    mma_f16(acc[mi][ni], af[mi], bf[ni]);
        }

        if (t + 1 < nT) CPA_WAIT0();
        __syncthreads();
    }

    OutT* Cp = C + (size_t)(blockIdx.y * 128 + mbase) * N + blockIdx.x * 128 + nbase;
    #pragma unroll
    for (int mi = 0; mi < 2; mi++) {
        const int r = mi * 16 + (lane >> 2);
        #pragma unroll
        for (int ni = 0; ni < 8; ni++) {
            const int c = ni * 8 + (lane & 3) * 2;
            if constexpr (sizeof(OutT) == 2) {
                *(uint32_t*)(Cp + (size_t)r       * N + c) = f2h2(acc[mi][ni][0], acc[mi][ni][1]);
                *(uint32_t*)(Cp + (size_t)(r + 8) * N + c) = f2h2(acc[mi][ni][2], acc[mi][ni][3]);
            } else {
                *(float2*)(Cp + (size_t)r       * N + c) = make_float2(acc[mi][ni][0], acc[mi][ni][1]);
                *(float2*)(Cp + (size_t)(r + 8) * N + c) = make_float2(acc[mi][ni][2], acc[mi][ni][3]);
            }
        }
    }
}

// ----------------------------------------------------------------------------
// RoPE (in place, fused qkv) using precomputed cos/sin tables.
// ----------------------------------------------------------------------------
__global__ __launch_bounds__(256) void rope2_kernel(
    __half* __restrict__ qkv, const float* __restrict__ ct, const float* __restrict__ st)
{
    const size_t half_n = (size_t)ROWS * HEADS * 64;
    size_t idx = (size_t)blockIdx.x * blockDim.x + threadIdx.x;
    int coff;
    if (idx >= half_n) {
        if (idx >= 2 * half_n) return;
        idx -= half_n;
        coff = INNER;
    } else {
        coff = 0;
    }
    const int d = (int)(idx & 63);
    const int h = (int)((idx >> 6) & (HEADS - 1));
    const int r = (int)(idx >> 10);
    const int n = r & (N_SEQ - 1);

    __half* base = qkv + (size_t)r * NQKV + coff + h * DHEAD;
    const float c1 = ct[n * DHEAD + d];
    const float s1 = st[n * DHEAD + d];
    const float c2 = ct[n * DHEAD + d + 64];
    const float s2 = st[n * DHEAD + d + 64];
    const float t1 = __half2float(base[d]);
    const float t2 = __half2float(base[d + 64]);
    base[d]      = __float2half(t1 * c1 - t2 * s1);
    base[d + 64] = __float2half(t2 * c2 + t1 * s2);
}

// ----------------------------------------------------------------------------
// Causal flash attention, fp16 m16n8k16, cp.async double-buffered KV.
// BM=64, 128 threads (4 warps) -> 2 CTAs/SM for cross-CTA pipe overlap.
// ----------------------------------------------------------------------------
#define FA_BM 64
#define FA_BN 64
#define FA_SK 136
#define FA_KVST (2 * FA_BN * FA_SK)                 // halfs per stage (K+V)
#define FA_SMEM (2 * FA_KVST * 2)                   // bytes (2 stages) = 69632

__global__ __launch_bounds__(128, 2) void attn_h16_kernel(
    const __half* __restrict__ QKV, __half* __restrict__ O)
{
    extern __shared__ __half smh[];
    const uint32_t sBase = smem_u32(smh);

    const int bh = blockIdx.y;
    const int b  = bh >> 4;
    const int h  = bh & 15;
    const int qt = gridDim.x - 1 - blockIdx.x;   // heavy tiles first

    const int tid  = threadIdx.x;
    const int lane = tid & 31;
    const int warp = tid >> 5;                   // 0..3

    // per-thread KV copy coords: 8 rows x 16B for K, same for V
    const int cr = tid >> 4;              // 0..7
    const int cc = (tid & 15) * 8;        // 0..120
    const __half* kvb = QKV + ((size_t)(b * N_SEQ)) * NQKV + INNER + h * DHEAD;

    // issue tile 0 loads
    {
        #pragma unroll
        for (int i = 0; i < 8; i++) {
            const int r = i * 8 + cr;
            const uint32_t kD = sBase + (uint32_t)(r * FA_SK + cc) * 2;
            cpa16(kD, kvb + (size_t)r * NQKV + cc);
            cpa16(kD + FA_BN * FA_SK * 2, kvb + (size_t)r * NQKV + INNER + cc);
        }
        CPA_COMMIT();
    }

    // Q fragments (overlap with tile-0 loads)
    const float qsf = 0.088388347648318447f * 1.4426950408889634f;
    const uint32_t qs2 = f2h2(qsf, qsf);
    uint32_t qf[8][4];
    {
        const __half* qb = QKV + ((size_t)(b * N_SEQ + qt * FA_BM + warp * 16 + (lane >> 2))) * NQKV
                               + h * DHEAD;
        #pragma unroll
        for (int ks = 0; ks < 8; ks++) {
            const int k0 = ks * 16 + 2 * (lane & 3);
            qf[ks][0] = hmul2(*(const uint32_t*)(qb + k0), qs2);
            qf[ks][1] = hmul2(*(const uint32_t*)(qb + 8 * NQKV + k0), qs2);
            qf[ks][2] = hmul2(*(const uint32_t*)(qb + k0 + 8), qs2);
            qf[ks][3] = hmul2(*(const uint32_t*)(qb + 8 * NQKV + k0 + 8), qs2);
        }
    }

    float oacc[16][4];
    #pragma unroll
    for (int nd = 0; nd < 16; nd++)
        #pragma unroll
        for (int e = 0; e < 4; e++) oacc[nd][e] = 0.f;

    float m0 = -INFINITY, m1 = -INFINITY, l0 = 0.f, l1 = 0.f;
    const int qrow0 = qt * FA_BM + warp * 16 + (lane >> 2);
    const int warp_min_row = qt * FA_BM + warp * 16;

    CPA_WAIT0();
    __syncthreads();

    const int ntiles = qt + 1;
    for (int kt = 0; kt < ntiles; kt++) {
        const int cur = kt & 1;

        // issue loads for tile kt+1 into the other stage
        if (kt + 1 < ntiles) {
            const int nxt = cur ^ 1;
            const __half* kvn = kvb + (size_t)((kt + 1) * FA_BN) * NQKV;
            const uint32_t stB = sBase + (uint32_t)nxt * FA_KVST * 2;
            #pragma unroll
            for (int i = 0; i < 8; i++) {
                const int r = i * 8 + cr;
                const uint32_t kD = stB + (uint32_t)(r * FA_SK + cc) * 2;
                cpa16(kD, kvn + (size_t)r * NQKV + cc);
                cpa16(kD + FA_BN * FA_SK * 2, kvn + (size_t)r * NQKV + INNER + cc);
            }
            CPA_COMMIT();
        }

        {
            const uint32_t ksBase = sBase + (uint32_t)cur * FA_KVST * 2;
            const uint32_t vsBase = ksBase + FA_BN * FA_SK * 2;

            // ---- S = Q @ K^T ---------------------------------------------
            float sacc[8][4];
            #pragma unroll
            for (int ni = 0; ni < 8; ni++)
                #pragma unroll
                for (int e = 0; e < 4; e++) sacc[ni][e] = 0.f;

            #pragma unroll
            for (int ks = 0; ks < 8; ks++) {
                uint32_t kf[8][2];
                #pragma unroll
                for (int np = 0; np < 4; np++) {
                    uint32_t td[4];
                    ldm_x4(td, ksBase + (uint32_t)(
                        (np * 16 + (lane & 7) + ((lane >> 4) << 3)) * FA_SK
                        + ks * 16 + (lane & 8)) * 2);
                    kf[2 * np][0]     = td[0];
                    kf[2 * np][1]     = td[1];
                    kf[2 * np + 1][0] = td[2];
                    kf[2 * np + 1][1] = td[3];
                }
                #pragma unroll
                for (int ni = 0; ni < 8; ni++)
                    mma_f16(sacc[ni], qf[ks], kf[ni]);
            }

            // ---- causal mask (diagonal tile only) ------------------------
            if (kt * FA_BN + FA_BN - 1 > warp_min_row) {
                #pragma unroll
                for (int ni = 0; ni < 8; ni++) {
                    const int cg = kt * FA_BN + ni * 8 + 2 * (lane & 3);
                    #pragma unroll
                    for (int e = 0; e < 4; e++) {
                        const int col = cg + (e & 1);
                        const int row = qrow0 + (e >> 1) * 8;
                        if (col > row) sacc[ni][e] = -INFINITY;
                    }
                }
            }

            // ---- online softmax (exp2 domain) ----------------------------
            float rmax0 = -INFINITY, rmax1 = -INFINITY;
            #pragma unroll
            for (int ni = 0; ni < 8; ni++) {
                rmax0 = fmaxf(rmax0, fmaxf(sacc[ni][0], sacc[ni][1]));
                rmax1 = fmaxf(rmax1, fmaxf(sacc[ni][2], sacc[ni][3]));
            }
            rmax0 = fmaxf(rmax0, __shfl_xor_sync(0xffffffffu, rmax0, 1));
            rmax0 = fmaxf(rmax0, __shfl_xor_sync(0xffffffffu, rmax0, 2));
            rmax1 = fmaxf(rmax1, __shfl_xor_sync(0xffffffffu, rmax1, 1));
            rmax1 = fmaxf(rmax1, __shfl_xor_sync(0xffffffffu, rmax1, 2));

            const float mn0 = fmaxf(m0, rmax0);
            const float mn1 = fmaxf(m1, rmax1);
            const float c0 = fex2(m0 - mn0);
            const float c1 = fex2(m1 - mn1);
            float ps0 = 0.f, ps1 = 0.f;
            #pragma unroll
            for (int ni = 0; ni < 8; ni++) {
                sacc[ni][0] = fex2(sacc[ni][0] - mn0);
                sacc[ni][1] = fex2(sacc[ni][1] - mn0);
                sacc[ni][2] = fex2(sacc[ni][2] - mn1);
                sacc[ni][3] = fex2(sacc[ni][3] - mn1);
                ps0 += sacc[ni][0] + sacc[ni][1];
                ps1 += sacc[ni][2] + sacc[ni][3];
            }
            ps0 += __shfl_xor_sync(0xffffffffu, ps0, 1);
            ps0 += __shfl_xor_sync(0xffffffffu, ps0, 2);
            ps1 += __shfl_xor_sync(0xffffffffu, ps1, 1);
            ps1 += __shfl_xor_sync(0xffffffffu, ps1, 2);
            l0 = l0 * c0 + ps0;
            l1 = l1 * c1 + ps1;
            m0 = mn0;
            m1 = mn1;
            #pragma unroll
            for (int nd = 0; nd < 16; nd++) {
                oacc[nd][0] *= c0;
                oacc[nd][1] *= c0;
                oacc[nd][2] *= c1;
                oacc[nd][3] *= c1;
            }

            // ---- O += P @ V  (C-frag == A-frag layout) -------------------
            #pragma unroll
            for (int j = 0; j < 4; j++) {
                uint32_t a[4];
                a[0] = f2h2(sacc[2 * j][0],     sacc[2 * j][1]);
                a[1] = f2h2(sacc[2 * j][2],     sacc[2 * j][3]);
                a[2] = f2h2(sacc[2 * j + 1][0], sacc[2 * j + 1][1]);
                a[3] = f2h2(sacc[2 * j + 1][2], sacc[2 * j + 1][3]);
                #pragma unroll
                for (int np = 0; np < 8; np++) {
                    uint32_t v[4];
                    ldm_x4_t(v, vsBase + (uint32_t)(
                        (j * 16 + (lane & 15)) * FA_SK
                        + np * 16 + ((lane >> 4) << 3)) * 2);
                    mma_f16(oacc[2 * np],     a, v);
                    mma_f16(oacc[2 * np + 1], a, v + 2);
                }
            }
        }

        if (kt + 1 < ntiles) CPA_WAIT0();
        __syncthreads();
    }

    // epilogue (fp16 out)
    const float inv0 = 1.f / l0;
    const float inv1 = 1.f / l1;
    __half* ob = O + ((size_t)(b * N_SEQ + qt * FA_BM + warp * 16 + (lane >> 2))) * INNER
                   + h * DHEAD + 2 * (lane & 3);
    #pragma unroll
    for (int nd = 0; nd < 16; nd++) {
        *(uint32_t*)(ob + nd * 8) = f2h2(oacc[nd][0] * inv0, oacc[nd][1] * inv0);
        *(uint32_t*)(ob + (size_t)8 * INNER + nd * 8) =
            f2h2(oacc[nd][2] * inv1, oacc[nd][3] * inv1);
    }
}

// ----------------------------------------------------------------------------
// Launch
// ----------------------------------------------------------------------------
extern "C" void kernel_launch(void* const* d_in, const int* in_sizes, int n_in,
                              void* d_out, int out_size)
{
    const float* x   = (const float*)d_in[0];
    const float* re  = (const float*)d_in[1];
    const float* g   = (const float*)d_in[2];
    const float* Wq  = (const float*)d_in[3];
    const float* Wkv = (const float*)d_in[4];
    const float* Wo  = (const float*)d_in[5];
    float* out = (float*)d_out;

    __half *xn, *qkv, *o, *wqkv, *wo;
    float *ct, *st;
    cudaGetSymbolAddress((void**)&xn,   g_xn);
    cudaGetSymbolAddress((void**)&qkv,  g_qkv);
    cudaGetSymbolAddress((void**)&o,    g_o);
    cudaGetSymbolAddress((void**)&wqkv, g_wqkv);
    cudaGetSymbolAddress((void**)&wo,   g_wo);
    cudaGetSymbolAddress((void**)&ct,   g_cos);
    cudaGetSymbolAddress((void**)&st,   g_sin);

    // 0) fused setup: weight cvt + cos/sin tables (one launch)
    setup_kernel<<<(SU_TOTAL + 255) / 256, 256>>>(Wq, Wkv, Wo, re, wqkv, wo, ct, st);

    // 1) RMSNorm
    rmsnorm_kernel<<<ROWS, 256>>>(x, g, xn);

    // 2) fused qkv projection
    dim3 gp(NQKV / 128, ROWS / 128);
    h16_gemm_kernel<__half><<<gp, 256>>>(ROWS, NQKV, DIM, xn, wqkv, qkv);

    // 3) RoPE (table-based)
    const size_t ropeN = 2 * (size_t)ROWS * HEADS * 64;
    const int ropeBlocks = (int)((ropeN + 255) / 256);
    rope2_kernel<<<ropeBlocks, 256>>>(qkv, ct, st);

    // 4) causal attention (BM=64, 2 CTAs/SM, cp.async KV pipeline)
    cudaFuncSetAttribute(attn_h16_kernel,
                         cudaFuncAttributeMaxDynamicSharedMemorySize, FA_SMEM);
    dim3 ga(N_SEQ / FA_BM, B * HEADS);
    attn_h16_kernel<<<ga, 128, FA_SMEM>>>(qkv, o);

    // 5) output projection
    dim3 go(DIM / 128, ROWS / 128);
    h16_gemm_kernel<float><<<go, 256>>>(ROWS, DIM, DIM, o, wo, out);
}